// round 16
// baseline (speedup 1.0000x reference)
#include <cuda_runtime.h>
#include <cstdint>

#define N_GRAPHS 256
#define N_NODES  100000
#define N_EDGES  1000000
#define EMB      64
#define EMB_RBF  16
#define TILE_CTA 128
#define N_TILES  ((N_EDGES + TILE_CTA - 1) / TILE_CTA)  // 7813
#define GRID_MAIN 740

// ---------------- device scratch (zero-initialized at module load; every
// kernel run leaves it zeroed again via the last-CTA reset) ----------------
__device__ float        g_acc6[N_GRAPHS * 6];
__device__ unsigned int g_cnt[N_GRAPHS];
__device__ unsigned int g_done;

// ---------------- helpers ----------------
__device__ __forceinline__ int load_idx(const void* p, int i, int is64) {
    if (is64) return (int)((const long long*)p)[i];
    return ((const int*)p)[i];
}

// bf16 hi/lo split of two fp32 -> packed bf16x2 (lower half = first value)
__device__ __forceinline__ void split_pack(float f0, float f1, uint32_t& hi, uint32_t& lo) {
    uint32_t h;
    asm("cvt.rn.bf16x2.f32 %0, %1, %2;" : "=r"(h) : "f"(f1), "f"(f0));
    float r0 = f0 - __uint_as_float(h << 16);
    float r1 = f1 - __uint_as_float(h & 0xFFFF0000u);
    uint32_t l;
    asm("cvt.rn.bf16x2.f32 %0, %1, %2;" : "=r"(l) : "f"(r1), "f"(r0));
    hi = h; lo = l;
}

// silu via single-MUFU tanh: x*sigmoid(x) = 0.5x + 0.5x*tanh(x/2)
__device__ __forceinline__ float silu(float x) {
    float t;
    asm("tanh.approx.f32 %0, %1;" : "=f"(t) : "f"(0.5f * x));
    float hx = 0.5f * x;
    return fmaf(hx, t, hx);
}

__device__ __forceinline__ void mma_bf16(float* d, const uint32_t* a, uint32_t b0, uint32_t b1) {
    asm volatile(
        "mma.sync.aligned.m16n8k16.row.col.f32.bf16.bf16.f32 "
        "{%0,%1,%2,%3}, {%4,%5,%6,%7}, {%8,%9}, {%0,%1,%2,%3};"
        : "+f"(d[0]), "+f"(d[1]), "+f"(d[2]), "+f"(d[3])
        : "r"(a[0]), "r"(a[1]), "r"(a[2]), "r"(a[3]), "r"(b0), "r"(b1));
}

// k-permutation: lane j4's fragment positions (phys k = 2j4,2j4+1,2j4+8,2j4+9
// within a 16-wide k-block) are assigned the CONTIGUOUS logical elements
// 4j4..4j4+3, so each lane's B data is one float4. A-fragments (W1, M) are
// built with the same mapping, making the contraction exact.

// ---------------- the single fused kernel ----------------
__global__ void __launch_bounds__(128)
main_kernel(const float* __restrict__ edge_emb,
            const void*  __restrict__ edge_index,
            const float* __restrict__ distance_vec,
            const void*  __restrict__ batch,
            const float* __restrict__ rbf,
            const float* __restrict__ W1,
            const float* __restrict__ W2,
            const float* __restrict__ Wrbf,
            const float* __restrict__ Wout,
            float* __restrict__ out) {
    __shared__ uint32_t afh[2048];          // W1^T hi fragments (8KB)
    __shared__ uint32_t afl[2048];          // W1^T lo fragments (8KB); scratch for M entries first
    __shared__ uint32_t afM[1024];          // M A-frags: hi at [mt*128+lane*4+r], lo at +512 (4KB)
    __shared__ unsigned int sCnt[N_GRAPHS];
    __shared__ float        sAcc[N_GRAPHS * 6];   // scratch for T first
    __shared__ int sFlag[2];                // [0]=is64, [1]=isLastCTA

    const int tid  = threadIdx.x;
    const int wid  = tid >> 5;
    const int lane = tid & 31;
    const int m4 = lane >> 2;      // 0..7
    const int j4 = lane & 3;       // 0..3

    // ---- dtype detect (warp 0): int64 iff all 64 leading odd words are 0 ----
    if (wid == 0) {
        const int* p = (const int*)edge_index;
        int nz = (p[2 * lane + 1] != 0) | (p[2 * (lane + 32) + 1] != 0);
        unsigned b = __ballot_sync(0xFFFFFFFFu, nz);
        if (lane == 0) sFlag[0] = (b == 0);
    }

    // ---- T[k][m] = Wout[m] * Wrbf[k][m] into sAcc scratch ----
    for (int i = tid; i < EMB_RBF * EMB; i += 128) {
        int k = i >> 6, m = i & 63;
        sAcc[i] = Wout[m] * Wrbf[k * EMB + m];
    }
    __syncthreads();
    const int is64 = sFlag[0];

    // ---- M[j][k] = sum_m W2[j][m] * T[k][m] into Mtmp (= afl scratch) ----
    {
        float* Mtmp = (float*)afl;
        int j = tid >> 1;
        int kbase = (tid & 1) * 8;
        const float4* W2r = (const float4*)(W2 + j * EMB);
        float acc[8];
        #pragma unroll
        for (int kk = 0; kk < 8; kk++) acc[kk] = 0.0f;
        #pragma unroll 4
        for (int mc = 0; mc < 16; mc++) {
            float4 wv = W2r[mc];
            int m = mc * 4;
            #pragma unroll
            for (int kk = 0; kk < 8; kk++) {
                const float* Tr = sAcc + (kbase + kk) * EMB + m;
                acc[kk] += wv.x * Tr[0] + wv.y * Tr[1] + wv.z * Tr[2] + wv.w * Tr[3];
            }
        }
        #pragma unroll
        for (int kk = 0; kk < 8; kk++) Mtmp[j * EMB_RBF + kbase + kk] = acc[kk];
    }
    __syncthreads();

    // ---- build M A-fragments (warp wid = mt tile), k-permuted ----
    {
        const float* Mtmp = (const float*)afl;
        int r0 = 16 * wid + m4;
        int kl = 4 * j4;     // logical base: lane's contiguous quad
        uint32_t h, l;
        split_pack(Mtmp[r0 * EMB_RBF + kl],           Mtmp[r0 * EMB_RBF + kl + 1],           h, l);
        afM[wid * 128 + lane * 4 + 0] = h; afM[512 + wid * 128 + lane * 4 + 0] = l;
        split_pack(Mtmp[(r0 + 8) * EMB_RBF + kl],     Mtmp[(r0 + 8) * EMB_RBF + kl + 1],     h, l);
        afM[wid * 128 + lane * 4 + 1] = h; afM[512 + wid * 128 + lane * 4 + 1] = l;
        split_pack(Mtmp[r0 * EMB_RBF + kl + 2],       Mtmp[r0 * EMB_RBF + kl + 3],           h, l);
        afM[wid * 128 + lane * 4 + 2] = h; afM[512 + wid * 128 + lane * 4 + 2] = l;
        split_pack(Mtmp[(r0 + 8) * EMB_RBF + kl + 2], Mtmp[(r0 + 8) * EMB_RBF + kl + 3],     h, l);
        afM[wid * 128 + lane * 4 + 3] = h; afM[512 + wid * 128 + lane * 4 + 3] = l;
    }
    __syncthreads();

    // ---- W1^T A-fragments (hi/lo), k-permuted; zero histograms ----
    for (int p = wid; p < 16; p += 4) {
        int mt = p >> 2, kt = p & 3;
        int r0 = 16 * mt + m4;
        int r1 = r0 + 8;
        int kl = 16 * kt + 4 * j4;   // logical contiguous quad
        uint32_t hi[4], lo[4];
        split_pack(W1[(kl    ) * EMB + r0], W1[(kl + 1) * EMB + r0], hi[0], lo[0]);
        split_pack(W1[(kl    ) * EMB + r1], W1[(kl + 1) * EMB + r1], hi[1], lo[1]);
        split_pack(W1[(kl + 2) * EMB + r0], W1[(kl + 3) * EMB + r0], hi[2], lo[2]);
        split_pack(W1[(kl + 2) * EMB + r1], W1[(kl + 3) * EMB + r1], hi[3], lo[3]);
        uint32_t base = (uint32_t)(p * 32 + lane) * 4;
        #pragma unroll
        for (int r = 0; r < 4; r++) { afh[base + r] = hi[r]; afl[base + r] = lo[r]; }
    }
    for (int i = tid; i < N_GRAPHS; i += 128) sCnt[i] = 0u;
    for (int i = tid; i < N_GRAPHS * 6; i += 128) sAcc[i] = 0.0f;
    __syncthreads();

    // ================= main loop =================
    for (int tile = blockIdx.x; tile < N_TILES; tile += GRID_MAIN) {
        const int base32 = tile * TILE_CTA + wid * 32;
        const int ntile = tile + GRID_MAIN;

        #pragma unroll 1
        for (int pair = 0; pair < 2; pair++) {
            const int base16 = base32 + pair * 16;

            // ---- L2 prefetch next tile (E rows + rbf rows) ----
            if (ntile < N_TILES) {
                int nb = ntile * TILE_CTA + wid * 32 + pair * 16;
                int pe = min(nb + (lane >> 1), N_EDGES - 1);
                const float* pf = edge_emb + (size_t)pe * EMB + (lane & 1) * 32;
                asm volatile("prefetch.global.L2 [%0];" :: "l"(pf));
                if (lane < 8) {
                    const float* pr = rbf + (size_t)min(nb, N_EDGES - 16) * EMB_RBF + lane * 32;
                    asm volatile("prefetch.global.L2 [%0];" :: "l"(pr));
                }
            }

            // ---- stage-1 B fragments: one float4 per kt per edge-subgroup ----
            uint32_t bhi[2][8], blo[2][8];
            #pragma unroll
            for (int g = 0; g < 2; g++) {
                int ec = min(base16 + 8 * g + m4, N_EDGES - 1);
                const float4* Ep = (const float4*)(edge_emb + (size_t)ec * EMB);
                #pragma unroll
                for (int kt = 0; kt < 4; kt++) {
                    float4 x = Ep[4 * kt + j4];   // logical quad 16kt+4j4..+3
                    split_pack(x.x, x.y, bhi[g][2 * kt], blo[g][2 * kt]);
                    split_pack(x.z, x.w, bhi[g][2 * kt + 1], blo[g][2 * kt + 1]);
                }
            }

            // ---- stage-1 MMAs: P = E @ W1, 3-term bf16 split, 16 edges ----
            float h0[16], h1[16];
            #pragma unroll
            for (int i = 0; i < 16; i++) { h0[i] = 0.0f; h1[i] = 0.0f; }
            #pragma unroll
            for (int mt = 0; mt < 4; mt++) {
                #pragma unroll
                for (int kt = 0; kt < 4; kt++) {
                    uint4 ah = *(const uint4*)&afh[((mt * 4 + kt) * 32 + lane) * 4];
                    uint4 al = *(const uint4*)&afl[((mt * 4 + kt) * 32 + lane) * 4];
                    mma_bf16(h0 + mt * 4, &ah.x, bhi[0][2 * kt], bhi[0][2 * kt + 1]);
                    mma_bf16(h0 + mt * 4, &al.x, bhi[0][2 * kt], bhi[0][2 * kt + 1]);
                    mma_bf16(h0 + mt * 4, &ah.x, blo[0][2 * kt], blo[0][2 * kt + 1]);
                    mma_bf16(h1 + mt * 4, &ah.x, bhi[1][2 * kt], bhi[1][2 * kt + 1]);
                    mma_bf16(h1 + mt * 4, &al.x, bhi[1][2 * kt], bhi[1][2 * kt + 1]);
                    mma_bf16(h1 + mt * 4, &ah.x, blo[1][2 * kt], blo[1][2 * kt + 1]);
                }
            }

            // ---- silu in fp32 (stays fp32 — no re-split) ----
            #pragma unroll
            for (int i = 0; i < 16; i++) {
                h0[i] = silu(h0[i]);
                h1[i] = silu(h1[i]);
            }

            // ---- V = M @ rbf^T : one float4 per edge-subgroup ----
            uint32_t rbh[2][2], rbl[2][2];
            #pragma unroll
            for (int g = 0; g < 2; g++) {
                int ec = min(base16 + 8 * g + m4, N_EDGES - 1);
                const float4* R = (const float4*)(rbf + (size_t)ec * EMB_RBF);
                float4 x = R[j4];                 // logical quad 4j4..4j4+3
                split_pack(x.x, x.y, rbh[g][0], rbl[g][0]);
                split_pack(x.z, x.w, rbh[g][1], rbl[g][1]);
            }
            float v0[16], v1[16];
            #pragma unroll
            for (int i = 0; i < 16; i++) { v0[i] = 0.0f; v1[i] = 0.0f; }
            #pragma unroll
            for (int mt = 0; mt < 4; mt++) {
                uint4 mh = *(const uint4*)&afM[mt * 128 + lane * 4];
                uint4 ml = *(const uint4*)&afM[512 + mt * 128 + lane * 4];
                mma_bf16(v0 + mt * 4, &mh.x, rbh[0][0], rbh[0][1]);
                mma_bf16(v0 + mt * 4, &ml.x, rbh[0][0], rbh[0][1]);
                mma_bf16(v0 + mt * 4, &mh.x, rbl[0][0], rbl[0][1]);
                mma_bf16(v1 + mt * 4, &mh.x, rbh[1][0], rbh[1][1]);
                mma_bf16(v1 + mt * 4, &ml.x, rbh[1][0], rbh[1][1]);
                mma_bf16(v1 + mt * 4, &mh.x, rbl[1][0], rbl[1][1]);
            }

            // ---- s = sum_f h*v : elementwise + butterfly over m4 lanes ----
            float acc[4] = {0.0f, 0.0f, 0.0f, 0.0f};   // [g*2 + b]
            #pragma unroll
            for (int mt = 0; mt < 4; mt++) {
                #pragma unroll
                for (int i = 0; i < 4; i++) {
                    acc[i & 1]       = fmaf(h0[mt * 4 + i], v0[mt * 4 + i], acc[i & 1]);
                    acc[2 + (i & 1)] = fmaf(h1[mt * 4 + i], v1[mt * 4 + i], acc[2 + (i & 1)]);
                }
            }
            #pragma unroll
            for (int k = 4; k <= 16; k <<= 1) {
                #pragma unroll
                for (int j = 0; j < 4; j++)
                    acc[j] += __shfl_xor_sync(0xFFFFFFFFu, acc[j], k);
            }

            // ---- geometry + smem histogram (16 active lanes: m4 < 4) ----
            if (m4 < 4) {
                int gg = m4 >> 1, b = m4 & 1;
                int e = base16 + 8 * gg + 2 * j4 + b;
                if (e < N_EDGES) {
                    float s = acc[m4];
                    int node = load_idx(edge_index, e, is64);
                    node = min(max(node, 0), N_NODES - 1);
                    int g = load_idx(batch, node, is64);
                    g = min(max(g, 0), N_GRAPHS - 1);
                    float dx = distance_vec[3 * e + 0];
                    float dy = distance_vec[3 * e + 1];
                    float dz = distance_vec[3 * e + 2];
                    float coef = s * rsqrtf(dx * dx + dy * dy + dz * dz);
                    float* ag = sAcc + g * 6;
                    atomicAdd(&sCnt[g], 1u);
                    atomicAdd(ag + 0, coef * dx * dx);
                    atomicAdd(ag + 1, coef * dy * dy);
                    atomicAdd(ag + 2, coef * dz * dz);
                    atomicAdd(ag + 3, coef * dx * dy);
                    atomicAdd(ag + 4, coef * dx * dz);
                    atomicAdd(ag + 5, coef * dy * dz);
                }
            }
        }
    }

    // ---- flush per-CTA partials ----
    __syncthreads();
    for (int i = tid; i < N_GRAPHS; i += 128) {
        unsigned int c = sCnt[i];
        if (c) atomicAdd(&g_cnt[i], c);
    }
    for (int i = tid; i < N_GRAPHS * 6; i += 128) {
        float v = sAcc[i];
        if (v != 0.0f) atomicAdd(&g_acc6[i], v);
    }
    __threadfence();
    __syncthreads();

    // ---- last CTA finalizes and re-zeroes global scratch ----
    if (tid == 0) {
        unsigned int v = atomicAdd(&g_done, 1u);
        sFlag[1] = (v == (unsigned int)(gridDim.x - 1));
    }
    __syncthreads();
    if (sFlag[1]) {
        for (int g = tid; g < N_GRAPHS; g += 128) {
            unsigned int c = *((volatile unsigned int*)&g_cnt[g]);
            float inv = c ? (1.0f / (float)c) : 0.0f;
            float xx = __ldcg(&g_acc6[g * 6 + 0]) * inv;
            float yy = __ldcg(&g_acc6[g * 6 + 1]) * inv;
            float zz = __ldcg(&g_acc6[g * 6 + 2]) * inv;
            float xy = __ldcg(&g_acc6[g * 6 + 3]) * inv;
            float xz = __ldcg(&g_acc6[g * 6 + 4]) * inv;
            float yz = __ldcg(&g_acc6[g * 6 + 5]) * inv;
            float* o = out + g * 9;
            o[0] = xx; o[1] = xy; o[2] = xz;
            o[3] = xy; o[4] = yy; o[5] = yz;
            o[6] = xz; o[7] = yz; o[8] = zz;
            g_cnt[g] = 0u;
            #pragma unroll
            for (int i = 0; i < 6; i++) g_acc6[g * 6 + i] = 0.0f;
        }
        if (tid == 0) g_done = 0u;
    }
}

// ---------------- launcher: ONE kernel ----------------
extern "C" void kernel_launch(void* const* d_in, const int* in_sizes, int n_in,
                              void* d_out, int out_size) {
    int i_ee = 0, i_ei = 1, i_dv = 2, i_b = 4, i_rbf = 5,
        i_w1 = 6, i_w2 = 7, i_wr = 8, i_wo = 9;
    int seen4096 = 0;
    for (int i = 0; i < n_in; i++) {
        int s = in_sizes[i];
        if      (s == 64000000) i_ee = i;
        else if (s == 2000000)  i_ei = i;
        else if (s == 3000000)  i_dv = i;
        else if (s == 100000)   i_b  = i;
        else if (s == 16000000) i_rbf = i;
        else if (s == 4096)     { if (seen4096++ == 0) i_w1 = i; else i_w2 = i; }
        else if (s == 1024)     i_wr = i;
        else if (s == 64)       i_wo = i;
    }

    main_kernel<<<GRID_MAIN, 128>>>(
        (const float*)d_in[i_ee], d_in[i_ei], (const float*)d_in[i_dv],
        d_in[i_b], (const float*)d_in[i_rbf], (const float*)d_in[i_w1],
        (const float*)d_in[i_w2], (const float*)d_in[i_wr], (const float*)d_in[i_wo],
        (float*)d_out);
    (void)out_size;
}

// round 17
// speedup vs baseline: 1.9420x; 1.9420x over previous
#include <cuda_runtime.h>
#include <cstdint>

#define N_GRAPHS 256
#define N_NODES  100000
#define N_EDGES  1000000
#define EMB      64
#define EMB_RBF  16
#define TILE_CTA 128
#define N_TILES  ((N_EDGES + TILE_CTA - 1) / TILE_CTA)  // 7813
#define GRID_MAIN 592

// ---------------- device scratch (zero-initialized at module load; every
// kernel run leaves it zeroed again via the last-CTA reset) ----------------
__device__ float        g_acc6[N_GRAPHS * 6];
__device__ unsigned int g_cnt[N_GRAPHS];
__device__ unsigned int g_done;

// ---------------- helpers ----------------
__device__ __forceinline__ int load_idx(const void* p, int i, int is64) {
    if (is64) return (int)((const long long*)p)[i];
    return ((const int*)p)[i];
}

// bf16 hi/lo split of two fp32 -> packed bf16x2 (lower half = first value)
__device__ __forceinline__ void split_pack(float f0, float f1, uint32_t& hi, uint32_t& lo) {
    uint32_t h;
    asm("cvt.rn.bf16x2.f32 %0, %1, %2;" : "=r"(h) : "f"(f1), "f"(f0));
    float r0 = f0 - __uint_as_float(h << 16);
    float r1 = f1 - __uint_as_float(h & 0xFFFF0000u);
    uint32_t l;
    asm("cvt.rn.bf16x2.f32 %0, %1, %2;" : "=r"(l) : "f"(r1), "f"(r0));
    hi = h; lo = l;
}

// silu via single-MUFU tanh: x*sigmoid(x) = 0.5x + 0.5x*tanh(x/2)
__device__ __forceinline__ float silu(float x) {
    float t;
    asm("tanh.approx.f32 %0, %1;" : "=f"(t) : "f"(0.5f * x));
    float hx = 0.5f * x;
    return fmaf(hx, t, hx);
}

__device__ __forceinline__ void mma_bf16(float* d, const uint32_t* a, uint32_t b0, uint32_t b1) {
    asm volatile(
        "mma.sync.aligned.m16n8k16.row.col.f32.bf16.bf16.f32 "
        "{%0,%1,%2,%3}, {%4,%5,%6,%7}, {%8,%9}, {%0,%1,%2,%3};"
        : "+f"(d[0]), "+f"(d[1]), "+f"(d[2]), "+f"(d[3])
        : "r"(a[0]), "r"(a[1]), "r"(a[2]), "r"(a[3]), "r"(b0), "r"(b1));
}

// k-permutation: lane j4's fragment positions (phys k = 2j4,2j4+1,2j4+8,2j4+9
// within a 16-wide k-block) are assigned the CONTIGUOUS logical elements
// 4j4..4j4+3, so each lane's B data is one float4. A-fragments (W1, M) are
// built with the same mapping, making the contraction exact.

// ---------------- the single fused kernel ----------------
__global__ void __launch_bounds__(128)
main_kernel(const float* __restrict__ edge_emb,
            const void*  __restrict__ edge_index,
            const float* __restrict__ distance_vec,
            const void*  __restrict__ batch,
            const float* __restrict__ rbf,
            const float* __restrict__ W1,
            const float* __restrict__ W2,
            const float* __restrict__ Wrbf,
            const float* __restrict__ Wout,
            float* __restrict__ out) {
    __shared__ uint32_t afh[2048];          // W1^T hi fragments (8KB)
    __shared__ uint32_t afl[2048];          // W1^T lo fragments (8KB); scratch for M entries first
    __shared__ uint32_t afM[1024];          // M A-frags: hi at [mt*128+lane*4+r], lo at +512 (4KB)
    __shared__ unsigned int sCnt[N_GRAPHS];
    __shared__ float        sAcc[N_GRAPHS * 6];   // scratch for T first
    __shared__ int sFlag[2];                // [0]=is64, [1]=isLastCTA

    const int tid  = threadIdx.x;
    const int wid  = tid >> 5;
    const int lane = tid & 31;
    const int m4 = lane >> 2;      // 0..7
    const int j4 = lane & 3;       // 0..3

    // ---- dtype detect (warp 0): int64 iff all 64 leading odd words are 0 ----
    if (wid == 0) {
        const int* p = (const int*)edge_index;
        int nz = (p[2 * lane + 1] != 0) | (p[2 * (lane + 32) + 1] != 0);
        unsigned b = __ballot_sync(0xFFFFFFFFu, nz);
        if (lane == 0) sFlag[0] = (b == 0);
    }

    // ---- T[k][m] = Wout[m] * Wrbf[k][m] into sAcc scratch ----
    for (int i = tid; i < EMB_RBF * EMB; i += 128) {
        int k = i >> 6, m = i & 63;
        sAcc[i] = Wout[m] * Wrbf[k * EMB + m];
    }
    __syncthreads();
    const int is64 = sFlag[0];

    // ---- M[j][k] = sum_m W2[j][m] * T[k][m] into Mtmp (= afl scratch) ----
    {
        float* Mtmp = (float*)afl;
        int j = tid >> 1;
        int kbase = (tid & 1) * 8;
        const float4* W2r = (const float4*)(W2 + j * EMB);
        float acc[8];
        #pragma unroll
        for (int kk = 0; kk < 8; kk++) acc[kk] = 0.0f;
        #pragma unroll 4
        for (int mc = 0; mc < 16; mc++) {
            float4 wv = W2r[mc];
            int m = mc * 4;
            #pragma unroll
            for (int kk = 0; kk < 8; kk++) {
                const float* Tr = sAcc + (kbase + kk) * EMB + m;
                acc[kk] += wv.x * Tr[0] + wv.y * Tr[1] + wv.z * Tr[2] + wv.w * Tr[3];
            }
        }
        #pragma unroll
        for (int kk = 0; kk < 8; kk++) Mtmp[j * EMB_RBF + kbase + kk] = acc[kk];
    }
    __syncthreads();

    // ---- build M A-fragments (warp wid = mt tile), k-permuted ----
    {
        const float* Mtmp = (const float*)afl;
        int r0 = 16 * wid + m4;
        int kl = 4 * j4;     // logical base: lane's contiguous quad
        uint32_t h, l;
        split_pack(Mtmp[r0 * EMB_RBF + kl],           Mtmp[r0 * EMB_RBF + kl + 1],           h, l);
        afM[wid * 128 + lane * 4 + 0] = h; afM[512 + wid * 128 + lane * 4 + 0] = l;
        split_pack(Mtmp[(r0 + 8) * EMB_RBF + kl],     Mtmp[(r0 + 8) * EMB_RBF + kl + 1],     h, l);
        afM[wid * 128 + lane * 4 + 1] = h; afM[512 + wid * 128 + lane * 4 + 1] = l;
        split_pack(Mtmp[r0 * EMB_RBF + kl + 2],       Mtmp[r0 * EMB_RBF + kl + 3],           h, l);
        afM[wid * 128 + lane * 4 + 2] = h; afM[512 + wid * 128 + lane * 4 + 2] = l;
        split_pack(Mtmp[(r0 + 8) * EMB_RBF + kl + 2], Mtmp[(r0 + 8) * EMB_RBF + kl + 3],     h, l);
        afM[wid * 128 + lane * 4 + 3] = h; afM[512 + wid * 128 + lane * 4 + 3] = l;
    }
    __syncthreads();

    // ---- W1^T A-fragments (hi/lo), k-permuted; zero histograms ----
    for (int p = wid; p < 16; p += 4) {
        int mt = p >> 2, kt = p & 3;
        int r0 = 16 * mt + m4;
        int r1 = r0 + 8;
        int kl = 16 * kt + 4 * j4;   // logical contiguous quad
        uint32_t hi[4], lo[4];
        split_pack(W1[(kl    ) * EMB + r0], W1[(kl + 1) * EMB + r0], hi[0], lo[0]);
        split_pack(W1[(kl    ) * EMB + r1], W1[(kl + 1) * EMB + r1], hi[1], lo[1]);
        split_pack(W1[(kl + 2) * EMB + r0], W1[(kl + 3) * EMB + r0], hi[2], lo[2]);
        split_pack(W1[(kl + 2) * EMB + r1], W1[(kl + 3) * EMB + r1], hi[3], lo[3]);
        uint32_t base = (uint32_t)(p * 32 + lane) * 4;
        #pragma unroll
        for (int r = 0; r < 4; r++) { afh[base + r] = hi[r]; afl[base + r] = lo[r]; }
    }
    for (int i = tid; i < N_GRAPHS; i += 128) sCnt[i] = 0u;
    for (int i = tid; i < N_GRAPHS * 6; i += 128) sAcc[i] = 0.0f;
    __syncthreads();

    // ================= main loop =================
    for (int tile = blockIdx.x; tile < N_TILES; tile += GRID_MAIN) {
        const int base32 = tile * TILE_CTA + wid * 32;
        const int ntile = tile + GRID_MAIN;

        #pragma unroll 1
        for (int pair = 0; pair < 2; pair++) {
            const int base16 = base32 + pair * 16;

            // ---- L2 prefetch next tile (E rows + rbf rows) ----
            if (ntile < N_TILES) {
                int nb = ntile * TILE_CTA + wid * 32 + pair * 16;
                int pe = min(nb + (lane >> 1), N_EDGES - 1);
                const float* pf = edge_emb + (size_t)pe * EMB + (lane & 1) * 32;
                asm volatile("prefetch.global.L2 [%0];" :: "l"(pf));
                if (lane < 8) {
                    const float* pr = rbf + (size_t)min(nb, N_EDGES - 16) * EMB_RBF + lane * 32;
                    asm volatile("prefetch.global.L2 [%0];" :: "l"(pr));
                }
            }

            // ---- stage-1 B fragments: one float4 per kt per edge-subgroup ----
            uint32_t bhi[2][8], blo[2][8];
            #pragma unroll
            for (int g = 0; g < 2; g++) {
                int ec = min(base16 + 8 * g + m4, N_EDGES - 1);
                const float4* Ep = (const float4*)(edge_emb + (size_t)ec * EMB);
                #pragma unroll
                for (int kt = 0; kt < 4; kt++) {
                    float4 x = Ep[4 * kt + j4];   // logical quad 16kt+4j4..+3
                    split_pack(x.x, x.y, bhi[g][2 * kt], blo[g][2 * kt]);
                    split_pack(x.z, x.w, bhi[g][2 * kt + 1], blo[g][2 * kt + 1]);
                }
            }

            // ---- stage-1 MMAs: P = E @ W1, 3-term bf16 split, 16 edges ----
            float h0[16], h1[16];
            #pragma unroll
            for (int i = 0; i < 16; i++) { h0[i] = 0.0f; h1[i] = 0.0f; }
            #pragma unroll
            for (int mt = 0; mt < 4; mt++) {
                #pragma unroll
                for (int kt = 0; kt < 4; kt++) {
                    uint4 ah = *(const uint4*)&afh[((mt * 4 + kt) * 32 + lane) * 4];
                    uint4 al = *(const uint4*)&afl[((mt * 4 + kt) * 32 + lane) * 4];
                    mma_bf16(h0 + mt * 4, &ah.x, bhi[0][2 * kt], bhi[0][2 * kt + 1]);
                    mma_bf16(h0 + mt * 4, &al.x, bhi[0][2 * kt], bhi[0][2 * kt + 1]);
                    mma_bf16(h0 + mt * 4, &ah.x, blo[0][2 * kt], blo[0][2 * kt + 1]);
                    mma_bf16(h1 + mt * 4, &ah.x, bhi[1][2 * kt], bhi[1][2 * kt + 1]);
                    mma_bf16(h1 + mt * 4, &al.x, bhi[1][2 * kt], bhi[1][2 * kt + 1]);
                    mma_bf16(h1 + mt * 4, &ah.x, blo[1][2 * kt], blo[1][2 * kt + 1]);
                }
            }

            // ---- silu in fp32 (stays fp32 — no re-split) ----
            #pragma unroll
            for (int i = 0; i < 16; i++) {
                h0[i] = silu(h0[i]);
                h1[i] = silu(h1[i]);
            }

            // ---- V = M @ rbf^T : one float4 per edge-subgroup ----
            uint32_t rbh[2][2], rbl[2][2];
            #pragma unroll
            for (int g = 0; g < 2; g++) {
                int ec = min(base16 + 8 * g + m4, N_EDGES - 1);
                const float4* R = (const float4*)(rbf + (size_t)ec * EMB_RBF);
                float4 x = R[j4];                 // logical quad 4j4..4j4+3
                split_pack(x.x, x.y, rbh[g][0], rbl[g][0]);
                split_pack(x.z, x.w, rbh[g][1], rbl[g][1]);
            }
            float v0[16], v1[16];
            #pragma unroll
            for (int i = 0; i < 16; i++) { v0[i] = 0.0f; v1[i] = 0.0f; }
            #pragma unroll
            for (int mt = 0; mt < 4; mt++) {
                uint4 mh = *(const uint4*)&afM[mt * 128 + lane * 4];
                uint4 ml = *(const uint4*)&afM[512 + mt * 128 + lane * 4];
                mma_bf16(v0 + mt * 4, &mh.x, rbh[0][0], rbh[0][1]);
                mma_bf16(v0 + mt * 4, &ml.x, rbh[0][0], rbh[0][1]);
                mma_bf16(v0 + mt * 4, &mh.x, rbl[0][0], rbl[0][1]);
                mma_bf16(v1 + mt * 4, &mh.x, rbh[1][0], rbh[1][1]);
                mma_bf16(v1 + mt * 4, &ml.x, rbh[1][0], rbh[1][1]);
                mma_bf16(v1 + mt * 4, &mh.x, rbl[1][0], rbl[1][1]);
            }

            // ---- s = sum_f h*v : elementwise + butterfly over m4 lanes ----
            float acc[4] = {0.0f, 0.0f, 0.0f, 0.0f};   // [g*2 + b]
            #pragma unroll
            for (int mt = 0; mt < 4; mt++) {
                #pragma unroll
                for (int i = 0; i < 4; i++) {
                    acc[i & 1]       = fmaf(h0[mt * 4 + i], v0[mt * 4 + i], acc[i & 1]);
                    acc[2 + (i & 1)] = fmaf(h1[mt * 4 + i], v1[mt * 4 + i], acc[2 + (i & 1)]);
                }
            }
            #pragma unroll
            for (int k = 4; k <= 16; k <<= 1) {
                #pragma unroll
                for (int j = 0; j < 4; j++)
                    acc[j] += __shfl_xor_sync(0xFFFFFFFFu, acc[j], k);
            }

            // ---- geometry + smem histogram (16 active lanes: m4 < 4) ----
            if (m4 < 4) {
                int gg = m4 >> 1, b = m4 & 1;
                int e = base16 + 8 * gg + 2 * j4 + b;
                if (e < N_EDGES) {
                    float s = acc[m4];
                    int node = load_idx(edge_index, e, is64);
                    node = min(max(node, 0), N_NODES - 1);
                    int g = load_idx(batch, node, is64);
                    g = min(max(g, 0), N_GRAPHS - 1);
                    float dx = distance_vec[3 * e + 0];
                    float dy = distance_vec[3 * e + 1];
                    float dz = distance_vec[3 * e + 2];
                    float coef = s * rsqrtf(dx * dx + dy * dy + dz * dz);
                    float* ag = sAcc + g * 6;
                    atomicAdd(&sCnt[g], 1u);
                    atomicAdd(ag + 0, coef * dx * dx);
                    atomicAdd(ag + 1, coef * dy * dy);
                    atomicAdd(ag + 2, coef * dz * dz);
                    atomicAdd(ag + 3, coef * dx * dy);
                    atomicAdd(ag + 4, coef * dx * dz);
                    atomicAdd(ag + 5, coef * dy * dz);
                }
            }
        }
    }

    // ---- flush per-CTA partials ----
    __syncthreads();
    for (int i = tid; i < N_GRAPHS; i += 128) {
        unsigned int c = sCnt[i];
        if (c) atomicAdd(&g_cnt[i], c);
    }
    for (int i = tid; i < N_GRAPHS * 6; i += 128) {
        float v = sAcc[i];
        if (v != 0.0f) atomicAdd(&g_acc6[i], v);
    }
    __threadfence();
    __syncthreads();

    // ---- last CTA finalizes and re-zeroes global scratch ----
    if (tid == 0) {
        unsigned int v = atomicAdd(&g_done, 1u);
        sFlag[1] = (v == (unsigned int)(gridDim.x - 1));
    }
    __syncthreads();
    if (sFlag[1]) {
        for (int g = tid; g < N_GRAPHS; g += 128) {
            unsigned int c = *((volatile unsigned int*)&g_cnt[g]);
            float inv = c ? (1.0f / (float)c) : 0.0f;
            float xx = __ldcg(&g_acc6[g * 6 + 0]) * inv;
            float yy = __ldcg(&g_acc6[g * 6 + 1]) * inv;
            float zz = __ldcg(&g_acc6[g * 6 + 2]) * inv;
            float xy = __ldcg(&g_acc6[g * 6 + 3]) * inv;
            float xz = __ldcg(&g_acc6[g * 6 + 4]) * inv;
            float yz = __ldcg(&g_acc6[g * 6 + 5]) * inv;
            float* o = out + g * 9;
            o[0] = xx; o[1] = xy; o[2] = xz;
            o[3] = xy; o[4] = yy; o[5] = yz;
            o[6] = xz; o[7] = yz; o[8] = zz;
            g_cnt[g] = 0u;
            #pragma unroll
            for (int i = 0; i < 6; i++) g_acc6[g * 6 + i] = 0.0f;
        }
        if (tid == 0) g_done = 0u;
    }
}

// ---------------- launcher: ONE kernel ----------------
extern "C" void kernel_launch(void* const* d_in, const int* in_sizes, int n_in,
                              void* d_out, int out_size) {
    int i_ee = 0, i_ei = 1, i_dv = 2, i_b = 4, i_rbf = 5,
        i_w1 = 6, i_w2 = 7, i_wr = 8, i_wo = 9;
    int seen4096 = 0;
    for (int i = 0; i < n_in; i++) {
        int s = in_sizes[i];
        if      (s == 64000000) i_ee = i;
        else if (s == 2000000)  i_ei = i;
        else if (s == 3000000)  i_dv = i;
        else if (s == 100000)   i_b  = i;
        else if (s == 16000000) i_rbf = i;
        else if (s == 4096)     { if (seen4096++ == 0) i_w1 = i; else i_w2 = i; }
        else if (s == 1024)     i_wr = i;
        else if (s == 64)       i_wo = i;
    }

    main_kernel<<<GRID_MAIN, 128>>>(
        (const float*)d_in[i_ee], d_in[i_ei], (const float*)d_in[i_dv],
        d_in[i_b], (const float*)d_in[i_rbf], (const float*)d_in[i_w1],
        (const float*)d_in[i_w2], (const float*)d_in[i_wr], (const float*)d_in[i_wo],
        (float*)d_out);
    (void)out_size;
}